// round 4
// baseline (speedup 1.0000x reference)
#include <cuda_runtime.h>

#define NPTS  1024
#define BTOT  32
#define RESV  48
#define SPIX  (RESV*RESV)
#define TILES 8
#define TROWS 6
#define NBINS 8
#define CAP   768            // per-(batch,rowtile) strip capacity
#define CAPC  513            // per col-bin capacity (padded: 513*4 words = 4 mod 32 banks)

// global scratch (no allocations allowed)
__device__ float4 g_strip[BTOT * TILES * CAP];   // (X, Y, f_second, f_max), index-ordered
__device__ int    g_cnt[BTOT * TILES];

// ---------------------------------------------------------------------------
// Kernel 1: 32 blocks x 1024 threads, 1 point/thread.
// Projection + top-2 feats + block minmax + normalize + ordered scatter into
// the <=2 row-tile strips whose x-band (6t-2, 6t+7) contains X.
// ---------------------------------------------------------------------------
__global__ void __launch_bounds__(1024)
prep_kernel(const float* __restrict__ xyz,
            const float* __restrict__ feats,
            const float* __restrict__ theta,
            const float* __restrict__ phi)
{
    __shared__ float red[32 * 4];          // per-warp minmax
    __shared__ int   wcnt[TILES * 32];     // [tile][warp]
    __shared__ int   wbase[TILES * 32];    // exclusive base  [tile][warp]

    int b = blockIdx.x;
    int k = b >> 2, m = b & 3;
    int tid = threadIdx.x, lane = tid & 31, wid = tid >> 5;

    float th = theta[m], ph = phi[m];
    float st = sinf(th), ct = cosf(th);
    float sp = sinf(ph), cp = cosf(ph);
    float U0 = -st, U1 = ct;
    float V0 = ct * sp, V1 = st * sp, V2 = cp;
    float cx = ct * cp, cy = st * cp, cz = sp;

    int g = k * NPTS + tid;
    float x = xyz[3 * g + 0];
    float y = xyz[3 * g + 1];
    float z = xyz[3 * g + 2];
    float dx = x - cx, dy = y - cy, dz = z - cz;
    float c0 = dx * U0 + dy * U1;
    float c1 = dx * V0 + dy * V1 + dz * V2;

    // top-2 of 20 (ascending last two of sort: [second, max])
    const float4* fr = (const float4*)(feats + (size_t)g * 20);
    float t1 = -1e30f, t2 = -1e30f;
#pragma unroll
    for (int q = 0; q < 5; q++) {
        float4 v = fr[q];
        float f;
        f = v.x; if (f > t1) { t2 = t1; t1 = f; } else if (f > t2) t2 = f;
        f = v.y; if (f > t1) { t2 = t1; t1 = f; } else if (f > t2) t2 = f;
        f = v.z; if (f > t1) { t2 = t1; t1 = f; } else if (f > t2) t2 = f;
        f = v.w; if (f > t1) { t2 = t1; t1 = f; } else if (f > t2) t2 = f;
    }

    // block minmax (order-invariant, exact)
    float mn0 = c0, mx0 = c0, mn1 = c1, mx1 = c1;
#pragma unroll
    for (int o = 16; o > 0; o >>= 1) {
        mn0 = fminf(mn0, __shfl_xor_sync(0xffffffffu, mn0, o));
        mx0 = fmaxf(mx0, __shfl_xor_sync(0xffffffffu, mx0, o));
        mn1 = fminf(mn1, __shfl_xor_sync(0xffffffffu, mn1, o));
        mx1 = fmaxf(mx1, __shfl_xor_sync(0xffffffffu, mx1, o));
    }
    if (lane == 0) {
        red[wid] = mn0; red[32 + wid] = mx0;
        red[64 + wid] = mn1; red[96 + wid] = mx1;
    }
    __syncthreads();
    mn0 = red[0]; mx0 = red[32]; mn1 = red[64]; mx1 = red[96];
#pragma unroll
    for (int w = 1; w < 32; w++) {
        mn0 = fminf(mn0, red[w]);      mx0 = fmaxf(mx0, red[32 + w]);
        mn1 = fminf(mn1, red[64 + w]); mx1 = fmaxf(mx1, red[96 + w]);
    }
    float ctr0 = (mx0 + mn0) * 0.5f;
    float ctr1 = (mx1 + mn1) * 0.5f;
    float sc0  = fmaxf(mx0 - mn0, 1e-5f) * 0.5f;
    float sc1  = fmaxf(mx1 - mn1, 1e-5f) * 0.5f;

    float X = (__fdiv_rn(c0 - ctr0, sc0) + 1.0f) * 19.2f + 4.8f;
    float Y = (__fdiv_rn(c1 - ctr1, sc1) + 1.0f) * 19.2f + 4.8f;

    // row-tile band ballots
    unsigned bal[TILES];
#pragma unroll
    for (int t = 0; t < TILES; t++) {
        bool kk = (X > (float)(TROWS * t) - 2.0f) &&
                  (X < (float)(TROWS * t + TROWS - 1) + 2.0f);
        bal[t] = __ballot_sync(0xffffffffu, kk);
        if (lane == 0) wcnt[t * 32 + wid] = __popc(bal[t]);
    }
    __syncthreads();

    // warp t scans 32 warp-counts for tile t (conflict-free: consecutive)
    if (wid < TILES) {
        int v = wcnt[wid * 32 + lane];
        int incl = v;
#pragma unroll
        for (int o = 1; o < 32; o <<= 1) {
            int n = __shfl_up_sync(0xffffffffu, incl, o);
            if (lane >= o) incl += n;
        }
        wbase[wid * 32 + lane] = incl - v;
        if (lane == 31) g_cnt[b * TILES + wid] = incl;
    }
    __syncthreads();

    // ordered scatter (<=2 tiles per point)
    unsigned lmask = (1u << lane) - 1u;
    float4 rec = make_float4(X, Y, t2, t1);
#pragma unroll
    for (int t = 0; t < TILES; t++) {
        if ((bal[t] >> lane) & 1u) {
            int idx = wbase[t * 32 + wid] + __popc(bal[t] & lmask);
            if (idx < CAP) g_strip[(b * TILES + t) * CAP + idx] = rec;
        }
    }
}

// ---------------------------------------------------------------------------
// Kernel 2: grid (8, 32), 288 threads (9 warps); 6 rows x 48 cols pixels.
// Ordered col-bin scatter of the strip list into shared, then ball query.
// dynamic smem:
//   [0, 65664)           float4 bins[8 * CAPC]
//   [65664, 66432)       int    cnt2[NBINS][24]    (24 = 3 rounds x 8 warps)
//   [66432, 67200)       uint   bal2[NBINS][24]
//   [67200, 67968)       int    sbase[NBINS][24]
//   [67968, 68000)       int    bintot[NBINS]
// ---------------------------------------------------------------------------
#define SMEM2 68000
extern __shared__ char smem_raw[];

__global__ void __launch_bounds__(288)
mask_kernel(float* __restrict__ out)
{
    float4*   bins   = (float4*)(smem_raw);
    int*      cnt2   = (int*)(smem_raw + 65664);
    unsigned* bal2   = (unsigned*)(smem_raw + 66432);
    int*      sbase  = (int*)(smem_raw + 67200);
    int*      bintot = (int*)(smem_raw + 67968);

    int t = blockIdx.x, b = blockIdx.y;
    int tid = threadIdx.x, lane = tid & 31, wid = tid >> 5;

    int total = min(g_cnt[b * TILES + t], CAP);
    const float4* strip = g_strip + (b * TILES + t) * CAP;

    // --- ballot phase: 3 rounds x 256 threads, index-ordered ---
    float4 rv[3];
    if (wid < 8) {
#pragma unroll
        for (int q = 0; q < 3; q++) {
            int pos = q * 256 + wid * 32 + lane;
            bool valid = pos < total;
            rv[q] = valid ? strip[pos] : make_float4(-100.f, -100.f, 0.f, 0.f);
#pragma unroll
            for (int c = 0; c < NBINS; c++) {
                bool kk = valid &&
                          (rv[q].y > (float)(TROWS * c) - 2.0f) &&
                          (rv[q].y < (float)(TROWS * c + TROWS - 1) + 2.0f);
                unsigned ba = __ballot_sync(0xffffffffu, kk);
                if (lane == 0) {
                    bal2[c * 24 + q * 8 + wid] = ba;
                    cnt2[c * 24 + q * 8 + wid] = __popc(ba);
                }
            }
        }
    }
    __syncthreads();

    // --- scan phase: warp c scans its 24 (round,warp) counts ---
    if (wid < NBINS) {
        int v = (lane < 24) ? cnt2[wid * 24 + lane] : 0;
        int incl = v;
#pragma unroll
        for (int o = 1; o < 32; o <<= 1) {
            int n = __shfl_up_sync(0xffffffffu, incl, o);
            if (lane >= o) incl += n;
        }
        if (lane < 24) sbase[wid * 24 + lane] = incl - v;
        if (lane == 23) bintot[wid] = incl;
    }
    __syncthreads();

    // --- ordered scatter into col bins ---
    if (wid < 8) {
        unsigned lmask = (1u << lane) - 1u;
#pragma unroll
        for (int q = 0; q < 3; q++) {
#pragma unroll
            for (int c = 0; c < NBINS; c++) {
                unsigned ba = bal2[c * 24 + q * 8 + wid];
                if ((ba >> lane) & 1u) {
                    int idx = sbase[c * 24 + q * 8 + wid] + __popc(ba & lmask);
                    if (idx < CAPC) bins[c * CAPC + idx] = rv[q];
                }
            }
        }
    }
    __syncthreads();

    // --- per-pixel ball query: first 16 in index order with d2 < 4 ---
    int row = tid / RESV;
    int j   = tid - row * RESV;
    int i   = t * TROWS + row;
    int c   = j / TROWS;
    int tot = min(bintot[c], CAPC);
    const float4* bp = bins + c * CAPC;

    float sx = (float)i, sy = (float)j;
    int nsel = 0;
    float f0 = 0.0f, f1 = 0.0f;
#pragma unroll 4
    for (int p = 0; p < tot; p++) {
        float4 q = bp[p];
        float ddx = sx - q.x;
        float ddy = sy - q.y;
        float d2 = fmaf(ddx, ddx, ddy * ddy);
        if (d2 < 4.0f && nsel < 16) {
            f0 += q.z; f1 += q.w; nsel++;
        }
    }

    float occ = fmaxf((float)nsel, 1.0f);
    float a0 = __fdiv_rn(f0, occ);
    float a1 = __fdiv_rn(f1, occ);
    float mxv = fmaxf(a0, a1);
    float e0 = expf(a0 - mxv);
    float e1 = expf(a1 - mxv);
    float s  = e0 + e1;
    float nf0 = __fdiv_rn(e0, s);
    float nf1 = __fdiv_rn(e1, s);
    float v = (nf0 == nf1) ? 0.0f : nf1 * 255.0f;

    int base = (b * 3) * SPIX + i * RESV + j;
    out[base]            = v;
    out[base + SPIX]     = v;
    out[base + 2 * SPIX] = v;
}

extern "C" void kernel_launch(void* const* d_in, const int* in_sizes, int n_in,
                              void* d_out, int out_size)
{
    const float* xyz   = (const float*)d_in[0];
    const float* feats = (const float*)d_in[1];
    const float* theta = (const float*)d_in[n_in - 2];
    const float* phi   = (const float*)d_in[n_in - 1];
    float* out = (float*)d_out;

    cudaFuncSetAttribute(mask_kernel,
                         cudaFuncAttributeMaxDynamicSharedMemorySize, SMEM2);

    prep_kernel<<<BTOT, 1024>>>(xyz, feats, theta, phi);
    mask_kernel<<<dim3(TILES, BTOT), 288, SMEM2>>>(out);
}